// round 3
// baseline (speedup 1.0000x reference)
#include <cuda_runtime.h>
#include <cstdint>
#include <math.h>

// Problem constants
#define B_  4
#define L_  1024
#define D_  768
#define H_  12
#define NE_ 42
#define M_  8
#define P_  (NE_*(NE_-1))      // 1722 ordered pairs
#define NPU 861                // NE*(NE-1)/2 unordered pairs (i<j)
#define EPS_H 1.2e-4f          // H * 1e-5 (eps folded through the /H)

// Expected element counts (for input disambiguation)
#define SZ_SO   (B_*L_*D_)        // 3145728
#define SZ_ATT  (B_*H_*L_*L_)     // 50331648
#define SZ_HTS  (B_*P_*2)         // 13776
#define SZ_MSK  (B_*NE_*M_)       // 1344 (mask and pos both)

// Scratch (static __device__ — no allocation allowed)
__device__ float g_ea[B_*H_*NE_*L_];       // entity_att  (8.25 MB)
__device__ float g_X [B_*NPU*L_];          // unnormalized pair attention (14.1 MB)
__device__ float g_scale[B_*NPU];          // 1/(sum_l X + H*eps)
__device__ int   g_p2p[B_*NE_*NE_];        // (i,j) -> ordered-pair row p
__device__ int   g_pos[B_*NE_*M_];         // mention_pos + OFFSET, as int32
__device__ int   g_ht [B_*P_*2];           // hts as int32

// ---------------------------------------------------------------------------
// K0: dtype-width detection + conversion + p2p build, all in ONE block.
// If the integer inputs are int64 (little-endian), every odd 32-bit word is 0
// (values are small non-negative). If int32, odd words are real indices and
// essentially never all-zero across 16 samples. Detect per-array, convert.
// ---------------------------------------------------------------------------
__global__ void k_prep(const int* __restrict__ posw, const int* __restrict__ htsw) {
    __shared__ int s_pos64, s_hts64;
    if (threadIdx.x == 0) {
        int nz = 0;
        for (int w = 1; w < 33; w += 2) nz |= posw[w];
        s_pos64 = (nz == 0) ? 1 : 0;
        nz = 0;
        for (int w = 1; w < 33; w += 2) nz |= htsw[w];
        s_hts64 = (nz == 0) ? 1 : 0;
    }
    __syncthreads();
    int sp = s_pos64 ? 2 : 1;
    for (int t = threadIdx.x; t < B_*NE_*M_; t += blockDim.x)
        g_pos[t] = posw[(size_t)t * sp] + 1;          // fold +OFFSET here
    int sh = s_hts64 ? 2 : 1;
    for (int t = threadIdx.x; t < B_*P_*2; t += blockDim.x)
        g_ht[t] = htsw[(size_t)t * sh];
    __syncthreads();
    // build reverse map (i,j) -> ordered pair row
    for (int t = threadIdx.x; t < B_*P_; t += blockDim.x) {
        int b = t / P_;
        int i = g_ht[(size_t)t * 2 + 0];
        int j = g_ht[(size_t)t * 2 + 1];
        g_p2p[(b * NE_ + i) * NE_ + j] = t - b * P_;
    }
}

// ---------------------------------------------------------------------------
// K1: entity_embed = logsumexp over active mentions.  grid = B*NE, block = D
// ---------------------------------------------------------------------------
__global__ void k_entity_embed(const float* __restrict__ so,
                               const float* __restrict__ mask,
                               float* __restrict__ out_ee) {
    int be = blockIdx.x;
    int b = be / NE_;
    int d = threadIdx.x;

    __shared__ int   s_row[M_];
    __shared__ float s_mk[M_];
    if (threadIdx.x < M_) {
        s_mk[threadIdx.x]  = mask[(size_t)be * M_ + threadIdx.x];
        s_row[threadIdx.x] = g_pos[be * M_ + threadIdx.x];
    }
    __syncthreads();

    float v[M_];
    float mx = -INFINITY;
#pragma unroll
    for (int m = 0; m < M_; m++) {
        if (s_mk[m] > 0.f) {
            v[m] = so[((size_t)b * L_ + s_row[m]) * D_ + d];
            mx = fmaxf(mx, v[m]);
        } else {
            v[m] = -INFINITY;
        }
    }
    float s = 0.f;
#pragma unroll
    for (int m = 0; m < M_; m++) s += __expf(v[m] - mx); // exp(-inf)=0
    out_ee[(size_t)be * D_ + d] = logf(s) + mx;
}

// ---------------------------------------------------------------------------
// K2: entity_att[b,h,e,l] = masked mean over mentions of attention rows
//     grid = B*NE*H, block = 256
// ---------------------------------------------------------------------------
__global__ void k_entity_att(const float* __restrict__ att,
                             const float* __restrict__ mask) {
    int id = blockIdx.x;           // (b*NE + e)*H + h
    int h  = id % H_;
    int be = id / H_;
    int b  = be / NE_;
    int e  = be % NE_;

    __shared__ int   s_row[M_];
    __shared__ float s_mk[M_];
    if (threadIdx.x < M_) {
        s_mk[threadIdx.x]  = mask[(size_t)be * M_ + threadIdx.x];
        s_row[threadIdx.x] = g_pos[be * M_ + threadIdx.x];
    }
    __syncthreads();

    float cnt = 0.f;
#pragma unroll
    for (int m = 0; m < M_; m++) cnt += s_mk[m];
    float inv = 1.f / cnt;

    const float* abase = att + ((size_t)(b * H_ + h)) * L_ * L_;
    float* ebase = g_ea + ((size_t)((b * H_ + h) * NE_ + e)) * L_;
    for (int l = threadIdx.x; l < L_; l += 256) {
        float acc = 0.f;
#pragma unroll
        for (int m = 0; m < M_; m++)
            if (s_mk[m] > 0.f) acc += abase[(size_t)s_row[m] * L_ + l];
        ebase[l] = acc * inv;
    }
}

// ---------------------------------------------------------------------------
// K3: unnormalized pair attention X[b,q,l] = sum_h ea_i * ea_j  (q: i<j)
//     + per-pair scale = 1/(sum_l X + H*eps).  grid = B*NPU, block = 256
// ---------------------------------------------------------------------------
__global__ void k_pair_att() {
    int bq = blockIdx.x;
    int b = bq / NPU, q = bq % NPU;

    // q -> (i,j), i<j, row-major upper triangle
    int i = 0, rem = q;
    while (rem >= NE_ - 1 - i) { rem -= NE_ - 1 - i; i++; }
    int j = i + 1 + rem;

    const float* ea_b = g_ea + (size_t)b * H_ * NE_ * L_;
    float* xrow = g_X + (size_t)bq * L_;

    float lsum = 0.f;
    for (int l = threadIdx.x; l < L_; l += 256) {
        float x = 0.f;
#pragma unroll
        for (int h = 0; h < H_; h++) {
            float a = ea_b[((size_t)h * NE_ + i) * L_ + l];
            float c = ea_b[((size_t)h * NE_ + j) * L_ + l];
            x += a * c;
        }
        xrow[l] = x;
        lsum += x;
    }
    __shared__ float red[256];
    red[threadIdx.x] = lsum;
    __syncthreads();
    for (int s = 128; s > 0; s >>= 1) {
        if (threadIdx.x < s) red[threadIdx.x] += red[threadIdx.x + s];
        __syncthreads();
    }
    if (threadIdx.x == 0)
        g_scale[bq] = 1.f / (red[0] + EPS_H);
}

// ---------------------------------------------------------------------------
// K4: batched GEMM  fm[b,q,:] = scale * (X[b,q,:] @ SO[b])   (M=861,K=1024,N=768)
//     Epilogue scatters each row to BOTH (i,j) and (j,i) h_t rows.
//     Tiling: BM=64, BN=128, BK=16, 256 threads, 4x8 microtile.
// ---------------------------------------------------------------------------
#define BM 64
#define BN 128
#define BK 16

__global__ __launch_bounds__(256)
void k_gemm(const float* __restrict__ so, float* __restrict__ out) {
    int b  = blockIdx.z;
    int m0 = blockIdx.y * BM;
    int n0 = blockIdx.x * BN;

    __shared__ float As[BK][BM];       // A transposed: As[k][m]
    __shared__ float Bs[BK][BN];

    int tid = threadIdx.x;
    int tx = tid & 15;                 // col group: 16 * 8 = 128
    int ty = tid >> 4;                 // row group: 16 * 4 = 64

    float acc[4][8];
#pragma unroll
    for (int r = 0; r < 4; r++)
#pragma unroll
        for (int c = 0; c < 8; c++) acc[r][c] = 0.f;

    const float* A  = g_X + (size_t)b * NPU * L_;
    const float* Bm = so  + (size_t)b * L_ * D_;

    int ar = tid >> 2;                 // 0..63  (A row within tile)
    int ak = (tid & 3) * 4;            // k offset 0,4,8,12

    for (int k0 = 0; k0 < L_; k0 += BK) {
        // --- load A tile (64 x 16), transposed into As ---
        float4 av = make_float4(0.f, 0.f, 0.f, 0.f);
        int gm = m0 + ar;
        if (gm < NPU)
            av = *(const float4*)&A[(size_t)gm * L_ + k0 + ak];
        As[ak + 0][ar] = av.x;
        As[ak + 1][ar] = av.y;
        As[ak + 2][ar] = av.z;
        As[ak + 3][ar] = av.w;

        // --- load B tile (16 x 128) ---
#pragma unroll
        for (int t = 0; t < 2; t++) {
            int idx = tid + t * 256;
            int br = idx >> 5;             // 0..15
            int bc = (idx & 31) * 4;       // 0..124
            *(float4*)&Bs[br][bc] =
                *(const float4*)&Bm[(size_t)(k0 + br) * D_ + n0 + bc];
        }
        __syncthreads();

#pragma unroll
        for (int k = 0; k < BK; k++) {
            float a0 = As[k][ty * 4 + 0];
            float a1 = As[k][ty * 4 + 1];
            float a2 = As[k][ty * 4 + 2];
            float a3 = As[k][ty * 4 + 3];
            float bb[8];
#pragma unroll
            for (int c = 0; c < 8; c++) bb[c] = Bs[k][tx * 8 + c];
#pragma unroll
            for (int c = 0; c < 8; c++) {
                acc[0][c] = fmaf(a0, bb[c], acc[0][c]);
                acc[1][c] = fmaf(a1, bb[c], acc[1][c]);
                acc[2][c] = fmaf(a2, bb[c], acc[2][c]);
                acc[3][c] = fmaf(a3, bb[c], acc[3][c]);
            }
        }
        __syncthreads();
    }

    // --- epilogue: scale + scatter to h_t rows (i,j) and (j,i) ---
    float* ht = out + (size_t)B_ * NE_ * D_;   // h_t region after entity_embed
#pragma unroll
    for (int rr = 0; rr < 4; rr++) {
        int q = m0 + ty * 4 + rr;
        if (q >= NPU) continue;
        float sc = g_scale[b * NPU + q];

        int i = 0, rem = q;
        while (rem >= NE_ - 1 - i) { rem -= NE_ - 1 - i; i++; }
        int j = i + 1 + rem;

        int pij = g_p2p[(b * NE_ + i) * NE_ + j];
        int pji = g_p2p[(b * NE_ + j) * NE_ + i];

        float4 v0 = make_float4(acc[rr][0] * sc, acc[rr][1] * sc,
                                acc[rr][2] * sc, acc[rr][3] * sc);
        float4 v1 = make_float4(acc[rr][4] * sc, acc[rr][5] * sc,
                                acc[rr][6] * sc, acc[rr][7] * sc);

        size_t o1 = ((size_t)(b * P_ + pij)) * D_ + n0 + tx * 8;
        size_t o2 = ((size_t)(b * P_ + pji)) * D_ + n0 + tx * 8;
        *(float4*)&ht[o1]     = v0;
        *(float4*)&ht[o1 + 4] = v1;
        *(float4*)&ht[o2]     = v0;
        *(float4*)&ht[o2 + 4] = v1;
    }
}

// ---------------------------------------------------------------------------
// Inputs identified by element count (unique except mask/pos, which keep
// their relative order in both plausible orderings: mask first, pos second).
// Integer width (int32 vs int64) is detected on-device in k_prep.
// ---------------------------------------------------------------------------
extern "C" void kernel_launch(void* const* d_in, const int* in_sizes, int n_in,
                              void* d_out, int out_size) {
    const float* so   = nullptr;
    const float* att  = nullptr;
    const float* mask = nullptr;
    const int*   posw = nullptr;   // raw words; width detected on device
    const int*   htsw = nullptr;

    for (int k = 0; k < n_in; k++) {
        int sz = in_sizes[k];
        if      (sz == SZ_SO)  so   = (const float*)d_in[k];
        else if (sz == SZ_ATT) att  = (const float*)d_in[k];
        else if (sz == SZ_HTS) htsw = (const int*)d_in[k];
        else if (sz == SZ_MSK) {
            if (!mask) mask = (const float*)d_in[k];   // first 1344 = mention_mask
            else       posw = (const int*)d_in[k];     // second 1344 = mention_pos
        }
    }
    float* out = (float*)d_out;

    k_prep<<<1, 1024>>>(posw, htsw);
    k_entity_embed<<<B_ * NE_, D_>>>(so, mask, out);
    k_entity_att<<<B_ * NE_ * H_, 256>>>(att, mask);
    k_pair_att<<<B_ * NPU, 256>>>();

    dim3 grid(D_ / BN, (NPU + BM - 1) / BM, B_);
    k_gemm<<<grid, 256>>>(so, out);
}

// round 6
// speedup vs baseline: 2.9667x; 2.9667x over previous
#include <cuda_runtime.h>
#include <cuda_bf16.h>
#include <cstdint>
#include <math.h>

// Problem constants
#define B_  4
#define L_  1024
#define D_  768
#define H_  12
#define NE_ 42
#define M_  8
#define P_  (NE_*(NE_-1))      // 1722 ordered pairs
#define NPU 861                // NE*(NE-1)/2 unordered pairs (i<j)
#define MP  896                // NPU padded to multiple of 128
#define EPS_H 1.2e-4f          // H * 1e-5

// Input element counts
#define SZ_SO   (B_*L_*D_)
#define SZ_ATT  (B_*H_*L_*L_)
#define SZ_HTS  (B_*P_*2)
#define SZ_MSK  (B_*NE_*M_)

// Scratch (__device__ globals zero-init; pad rows >= NPU stay zero)
__device__ float          g_ea[B_*H_*NE_*L_];     // entity_att
__device__ __nv_bfloat16  g_Xhi[B_*MP*L_];        // pair att hi  [b,q,l]
__device__ __nv_bfloat16  g_Xlo[B_*MP*L_];
__device__ __nv_bfloat16  g_Bhi[B_*D_*L_];        // SO^T hi      [b,d,l]
__device__ __nv_bfloat16  g_Blo[B_*D_*L_];
__device__ float          g_scale[B_*NPU];
__device__ int            g_p2p[B_*NE_*NE_];
__device__ int            g_pos[B_*NE_*M_];
__device__ int            g_ht [B_*P_*2];

// ===========================================================================
// PTX helpers (baseline ISA only — NO tcgen05: harness targets sm_103 non-'a')
// ===========================================================================
__device__ __forceinline__ uint32_t smem_u32(const void* p) {
    uint32_t a;
    asm("{ .reg .u64 t; cvta.to.shared.u64 t, %1; cvt.u32.u64 %0, t; }"
        : "=r"(a) : "l"(p));
    return a;
}
__device__ __forceinline__ void ldm_x4(uint32_t* r, uint32_t addr) {
    asm volatile("ldmatrix.sync.aligned.m8n8.x4.shared.b16 {%0,%1,%2,%3}, [%4];"
        : "=r"(r[0]), "=r"(r[1]), "=r"(r[2]), "=r"(r[3]) : "r"(addr));
}
__device__ __forceinline__ void mma_bf16(float* d, const uint32_t* a,
                                         const uint32_t* b) {
    asm volatile("mma.sync.aligned.m16n8k16.row.col.f32.bf16.bf16.f32 "
        "{%0,%1,%2,%3}, {%4,%5,%6,%7}, {%8,%9}, {%0,%1,%2,%3};"
        : "+f"(d[0]), "+f"(d[1]), "+f"(d[2]), "+f"(d[3])
        : "r"(a[0]), "r"(a[1]), "r"(a[2]), "r"(a[3]), "r"(b[0]), "r"(b[1]));
}

// ===========================================================================
// K0: int width detect + convert + p2p map (one block)
// ===========================================================================
__global__ void k_prep(const int* __restrict__ posw, const int* __restrict__ htsw) {
    __shared__ int s_pos64, s_hts64;
    if (threadIdx.x == 0) {
        int nz = 0;
        for (int w = 1; w < 33; w += 2) nz |= posw[w];
        s_pos64 = (nz == 0) ? 1 : 0;
        nz = 0;
        for (int w = 1; w < 33; w += 2) nz |= htsw[w];
        s_hts64 = (nz == 0) ? 1 : 0;
    }
    __syncthreads();
    int sp = s_pos64 ? 2 : 1;
    for (int t = threadIdx.x; t < B_*NE_*M_; t += blockDim.x)
        g_pos[t] = posw[(size_t)t * sp] + 1;          // fold +OFFSET
    int sh = s_hts64 ? 2 : 1;
    for (int t = threadIdx.x; t < B_*P_*2; t += blockDim.x)
        g_ht[t] = htsw[(size_t)t * sh];
    __syncthreads();
    for (int t = threadIdx.x; t < B_*P_; t += blockDim.x) {
        int b = t / P_;
        int i = g_ht[(size_t)t * 2 + 0];
        int j = g_ht[(size_t)t * 2 + 1];
        g_p2p[(b * NE_ + i) * NE_ + j] = t - b * P_;
    }
}

// ===========================================================================
// K1: entity_embed  (grid = B*NE, block = D)
// ===========================================================================
__global__ void k_entity_embed(const float* __restrict__ so,
                               const float* __restrict__ mask,
                               float* __restrict__ out_ee) {
    int be = blockIdx.x;
    int b = be / NE_;
    int d = threadIdx.x;

    __shared__ int   s_row[M_];
    __shared__ float s_mk[M_];
    if (threadIdx.x < M_) {
        s_mk[threadIdx.x]  = mask[(size_t)be * M_ + threadIdx.x];
        s_row[threadIdx.x] = g_pos[be * M_ + threadIdx.x];
    }
    __syncthreads();

    float v[M_];
    float mx = -INFINITY;
#pragma unroll
    for (int m = 0; m < M_; m++) {
        if (s_mk[m] > 0.f) {
            v[m] = so[((size_t)b * L_ + s_row[m]) * D_ + d];
            mx = fmaxf(mx, v[m]);
        } else v[m] = -INFINITY;
    }
    float s = 0.f;
#pragma unroll
    for (int m = 0; m < M_; m++) s += __expf(v[m] - mx);
    out_ee[(size_t)be * D_ + d] = logf(s) + mx;
}

// ===========================================================================
// K2: entity_att  (grid = B*NE*H, block = 256)
// ===========================================================================
__global__ void k_entity_att(const float* __restrict__ att,
                             const float* __restrict__ mask) {
    int id = blockIdx.x;
    int h  = id % H_;
    int be = id / H_;
    int b  = be / NE_;
    int e  = be % NE_;

    __shared__ int   s_row[M_];
    __shared__ float s_mk[M_];
    if (threadIdx.x < M_) {
        s_mk[threadIdx.x]  = mask[(size_t)be * M_ + threadIdx.x];
        s_row[threadIdx.x] = g_pos[be * M_ + threadIdx.x];
    }
    __syncthreads();

    float cnt = 0.f;
#pragma unroll
    for (int m = 0; m < M_; m++) cnt += s_mk[m];
    float inv = 1.f / cnt;

    const float* abase = att + ((size_t)(b * H_ + h)) * L_ * L_;
    float* ebase = g_ea + ((size_t)((b * H_ + h) * NE_ + e)) * L_;
    for (int l = threadIdx.x; l < L_; l += 256) {
        float acc = 0.f;
#pragma unroll
        for (int m = 0; m < M_; m++)
            if (s_mk[m] > 0.f) acc += abase[(size_t)s_row[m] * L_ + l];
        ebase[l] = acc * inv;
    }
}

// ===========================================================================
// K2b: transpose + bf16-split SO -> g_Bhi/g_Blo [b, d, l]
// ===========================================================================
__global__ void k_transpose(const float* __restrict__ so) {
    __shared__ float t[32][33];
    int b  = blockIdx.z;
    int l0 = blockIdx.x * 32;
    int d0 = blockIdx.y * 32;
    int tx = threadIdx.x, ty = threadIdx.y;

#pragma unroll
    for (int i = 0; i < 4; i++) {
        int l = l0 + ty + i * 8;
        t[ty + i * 8][tx] = so[((size_t)b * L_ + l) * D_ + d0 + tx];
    }
    __syncthreads();
#pragma unroll
    for (int i = 0; i < 4; i++) {
        int d = d0 + ty + i * 8;
        float v = t[tx][ty + i * 8];
        __nv_bfloat16 hi = __float2bfloat16(v);
        __nv_bfloat16 lo = __float2bfloat16(v - __bfloat162float(hi));
        size_t o = ((size_t)(b * D_ + d)) * L_ + l0 + tx;
        g_Bhi[o] = hi;
        g_Blo[o] = lo;
    }
}

// ===========================================================================
// K3: pair attention X (bf16 hi/lo) + scale   (grid = B*NPU, block = 256)
// ===========================================================================
__global__ void k_pair_att() {
    int bq = blockIdx.x;
    int b = bq / NPU, q = bq % NPU;

    int i = 0, rem = q;
    while (rem >= NE_ - 1 - i) { rem -= NE_ - 1 - i; i++; }
    int j = i + 1 + rem;

    const float* ea_b = g_ea + (size_t)b * H_ * NE_ * L_;
    size_t rowbase = ((size_t)(b * MP + q)) * L_;

    float lsum = 0.f;
    for (int l = threadIdx.x; l < L_; l += 256) {
        float x = 0.f;
#pragma unroll
        for (int h = 0; h < H_; h++) {
            float a = ea_b[((size_t)h * NE_ + i) * L_ + l];
            float c = ea_b[((size_t)h * NE_ + j) * L_ + l];
            x += a * c;
        }
        __nv_bfloat16 hi = __float2bfloat16(x);
        __nv_bfloat16 lo = __float2bfloat16(x - __bfloat162float(hi));
        g_Xhi[rowbase + l] = hi;
        g_Xlo[rowbase + l] = lo;
        lsum += x;
    }
    __shared__ float red[256];
    red[threadIdx.x] = lsum;
    __syncthreads();
    for (int s = 128; s > 0; s >>= 1) {
        if (threadIdx.x < s) red[threadIdx.x] += red[threadIdx.x + s];
        __syncthreads();
    }
    if (threadIdx.x == 0)
        g_scale[bq] = 1.f / (red[0] + EPS_H);
}

// ===========================================================================
// K4: mma.sync bf16x3 GEMM.  CTA tile 128x128, 256 thr (8 warps, 2m x 4n),
//     warp tile 64x32, BK=32.  grid = (D/128, MP/128, B).
// SMEM layout (dynamic, 67584 B):
//   during compute: A_hi[128][40]b16 @0, A_lo @10240, B_hi @20480, B_lo @30720
//   epilogue:       C[128][132]f32   @0
// ===========================================================================
#define TSTRIDE 40          // padded SMEM row stride in bf16 (80B, bank-safe)
#define SA_HI 0
#define SA_LO 10240
#define SB_HI 20480
#define SB_LO 30720
#define CSTRIDE 132
#define SM_TOT (128*CSTRIDE*4)   // 67584

__global__ __launch_bounds__(256)
void k_gemm_mma(float* __restrict__ out) {
    extern __shared__ char smem[];
    uint32_t sb = smem_u32(smem);

    int tid = threadIdx.x;
    int wid = tid >> 5, lane = tid & 31;
    int gid = lane >> 2, tig = lane & 3;     // mma fragment coords
    int wm = wid & 1, wn = wid >> 1;         // warp grid 2(m) x 4(n)
    int b  = blockIdx.z;
    int m0 = blockIdx.y * 128;
    int n0 = blockIdx.x * 128;

    const uint4* Ahi = (const uint4*)g_Xhi;  // row stride 128 uint4
    const uint4* Alo = (const uint4*)g_Xlo;
    const uint4* Bhi = (const uint4*)g_Bhi;
    const uint4* Blo = (const uint4*)g_Blo;
    int arow0 = (b * MP + m0) * 128;
    int brow0 = (b * D_ + n0) * 128;

    float acc[4][4][4];
#pragma unroll
    for (int mt = 0; mt < 4; mt++)
#pragma unroll
        for (int nt = 0; nt < 4; nt++)
#pragma unroll
            for (int r = 0; r < 4; r++) acc[mt][nt][r] = 0.f;

    // ldmatrix base addresses (lane-dependent), computed once.
    int sub = lane >> 3, lrow = lane & 7;
    // A x4: groups (m+0,k+0),(m+8,k+0),(m+0,k+8),(m+8,k+8)
    int a_r = wm * 64 + lrow + (sub & 1) * 8;
    int a_k = (sub >> 1) * 8;
    // B x4: groups (n+0,k+0),(n+0,k+8),(n+8,k+0),(n+8,k+8)
    int b_r = wn * 32 + lrow + (sub >> 1) * 8;
    int b_k = (sub & 1) * 8;

    // global load indices: 512 uint4 per tile, thread does idx=tid, tid+256
    int g_row  = tid >> 2, g_seg = tid & 3;          // rows 0..63
    int s_off  = g_row * (TSTRIDE * 2) + g_seg * 16; // smem byte offset
    int s_off2 = (g_row + 64) * (TSTRIDE * 2) + g_seg * 16;

    for (int it = 0; it < 32; it++) {
        int ku = it * 4;    // uint4 offset of this k-chunk
        __syncthreads();    // previous compute done before overwrite

        {
            int gi1 = arow0 + g_row * 128 + ku + g_seg;
            int gi2 = gi1 + 64 * 128;
            *(uint4*)(smem + SA_HI + s_off)  = Ahi[gi1];
            *(uint4*)(smem + SA_HI + s_off2) = Ahi[gi2];
            *(uint4*)(smem + SA_LO + s_off)  = Alo[gi1];
            *(uint4*)(smem + SA_LO + s_off2) = Alo[gi2];
            int bi1 = brow0 + g_row * 128 + ku + g_seg;
            int bi2 = bi1 + 64 * 128;
            *(uint4*)(smem + SB_HI + s_off)  = Bhi[bi1];
            *(uint4*)(smem + SB_HI + s_off2) = Bhi[bi2];
            *(uint4*)(smem + SB_LO + s_off)  = Blo[bi1];
            *(uint4*)(smem + SB_LO + s_off2) = Blo[bi2];
        }
        __syncthreads();

#pragma unroll
        for (int ks = 0; ks < 2; ks++) {
            uint32_t ah[4][4], al[4][4], bh[4][2], bl[4][2];
            int kofs = (ks * 16 + a_k) * 2;
#pragma unroll
            for (int mt = 0; mt < 4; mt++) {
                uint32_t ad = sb + ((a_r + mt * 16) * (TSTRIDE * 2)) + kofs;
                ldm_x4(ah[mt], ad + SA_HI);
                ldm_x4(al[mt], ad + SA_LO);
            }
            int kofsb = (ks * 16 + b_k) * 2;
#pragma unroll
            for (int np = 0; np < 2; np++) {
                uint32_t bd = sb + ((b_r + np * 16) * (TSTRIDE * 2)) + kofsb;
                uint32_t t4[4];
                ldm_x4(t4, bd + SB_HI);
                bh[np*2][0] = t4[0]; bh[np*2][1] = t4[1];
                bh[np*2+1][0] = t4[2]; bh[np*2+1][1] = t4[3];
                ldm_x4(t4, bd + SB_LO);
                bl[np*2][0] = t4[0]; bl[np*2][1] = t4[1];
                bl[np*2+1][0] = t4[2]; bl[np*2+1][1] = t4[3];
            }
#pragma unroll
            for (int mt = 0; mt < 4; mt++)
#pragma unroll
                for (int nt = 0; nt < 4; nt++) {
                    mma_bf16(acc[mt][nt], ah[mt], bh[nt]);
                    mma_bf16(acc[mt][nt], ah[mt], bl[nt]);
                    mma_bf16(acc[mt][nt], al[mt], bh[nt]);
                }
        }
    }

    // -------- epilogue: acc -> SMEM C, then scaled dual scatter --------
    __shared__ float s_sc[128];
    __shared__ int   s_p1[128], s_p2[128];

    __syncthreads();   // all ldmatrix reads done; smem reused for C

    float* C = (float*)smem;
#pragma unroll
    for (int mt = 0; mt < 4; mt++) {
        int rm = wm * 64 + mt * 16 + gid;
#pragma unroll
        for (int nt = 0; nt < 4; nt++) {
            int cn = wn * 32 + nt * 8 + tig * 2;
            *(float2*)&C[rm * CSTRIDE + cn]       = make_float2(acc[mt][nt][0], acc[mt][nt][1]);
            *(float2*)&C[(rm + 8) * CSTRIDE + cn] = make_float2(acc[mt][nt][2], acc[mt][nt][3]);
        }
    }
    if (tid < 128) {
        int q = m0 + tid;
        if (q < NPU) {
            s_sc[tid] = g_scale[b * NPU + q];
            int i = 0, rem = q;
            while (rem >= NE_ - 1 - i) { rem -= NE_ - 1 - i; i++; }
            int j = i + 1 + rem;
            s_p1[tid] = g_p2p[(b * NE_ + i) * NE_ + j];
            s_p2[tid] = g_p2p[(b * NE_ + j) * NE_ + i];
        }
    }
    __syncthreads();

    int r    = tid >> 1;
    int half = (tid & 1) * 64;
    int q = m0 + r;
    if (q < NPU) {
        float sc = s_sc[r];
        float* ht = out + (size_t)B_ * NE_ * D_;
        size_t o1 = ((size_t)(b * P_ + s_p1[r])) * D_ + n0 + half;
        size_t o2 = ((size_t)(b * P_ + s_p2[r])) * D_ + n0 + half;
        const float* crow = &C[r * CSTRIDE + half];
#pragma unroll
        for (int c = 0; c < 64; c += 4) {
            float4 v = make_float4(crow[c] * sc, crow[c + 1] * sc,
                                   crow[c + 2] * sc, crow[c + 3] * sc);
            *(float4*)&ht[o1 + c] = v;
            *(float4*)&ht[o2 + c] = v;
        }
    }
}

// ===========================================================================
extern "C" void kernel_launch(void* const* d_in, const int* in_sizes, int n_in,
                              void* d_out, int out_size) {
    const float* so   = nullptr;
    const float* att  = nullptr;
    const float* mask = nullptr;
    const int*   posw = nullptr;
    const int*   htsw = nullptr;

    for (int k = 0; k < n_in; k++) {
        int sz = in_sizes[k];
        if      (sz == SZ_SO)  so   = (const float*)d_in[k];
        else if (sz == SZ_ATT) att  = (const float*)d_in[k];
        else if (sz == SZ_HTS) htsw = (const int*)d_in[k];
        else if (sz == SZ_MSK) {
            if (!mask) mask = (const float*)d_in[k];
            else       posw = (const int*)d_in[k];
        }
    }
    float* out = (float*)d_out;

    static int smem_set = 0;
    if (!smem_set) {
        cudaFuncSetAttribute(k_gemm_mma,
                             cudaFuncAttributeMaxDynamicSharedMemorySize, SM_TOT);
        smem_set = 1;
    }

    k_prep<<<1, 1024>>>(posw, htsw);
    k_entity_embed<<<B_ * NE_, D_>>>(so, mask, out);
    {
        dim3 g(L_ / 32, D_ / 32, B_);
        dim3 t(32, 8);
        k_transpose<<<g, t>>>(so);
    }
    k_entity_att<<<B_ * NE_ * H_, 256>>>(att, mask);
    k_pair_att<<<B_ * NPU, 256>>>();

    dim3 grid(D_ / 128, MP / 128, B_);
    k_gemm_mma<<<grid, 256, SM_TOT>>>(out);
}

// round 7
// speedup vs baseline: 3.8477x; 1.2970x over previous
#include <cuda_runtime.h>
#include <cuda_bf16.h>
#include <cstdint>
#include <math.h>

// Problem constants
#define B_  4
#define L_  1024
#define D_  768
#define H_  12
#define NE_ 42
#define M_  8
#define P_  (NE_*(NE_-1))      // 1722 ordered pairs
#define NPU 861                // unordered pairs (i<j)
#define MP  896                // NPU padded to 128
#define EPS_H 1.2e-4f

// Input element counts
#define SZ_SO   (B_*L_*D_)
#define SZ_ATT  (B_*H_*L_*L_)
#define SZ_HTS  (B_*P_*2)
#define SZ_MSK  (B_*NE_*M_)

// Scratch (zero-init; pad rows >= NPU stay zero)
__device__ float          g_ea[B_*H_*NE_*L_];
__device__ __nv_bfloat16  g_Xhi[B_*MP*L_];
__device__ __nv_bfloat16  g_Xlo[B_*MP*L_];
__device__ __nv_bfloat16  g_Bhi[B_*D_*L_];
__device__ __nv_bfloat16  g_Blo[B_*D_*L_];
__device__ float          g_scale[B_*NPU];
__device__ int            g_p2p[B_*NE_*NE_];
__device__ int            g_pos[B_*NE_*M_];
__device__ int            g_ht [B_*P_*2];

// ===========================================================================
// PTX helpers (baseline ISA only — sm_103 non-'a' target: no tcgen05)
// ===========================================================================
__device__ __forceinline__ uint32_t smem_u32(const void* p) {
    uint32_t a;
    asm("{ .reg .u64 t; cvta.to.shared.u64 t, %1; cvt.u32.u64 %0, t; }"
        : "=r"(a) : "l"(p));
    return a;
}
__device__ __forceinline__ void ldm_x4(uint32_t* r, uint32_t addr) {
    asm volatile("ldmatrix.sync.aligned.m8n8.x4.shared.b16 {%0,%1,%2,%3}, [%4];"
        : "=r"(r[0]), "=r"(r[1]), "=r"(r[2]), "=r"(r[3]) : "r"(addr));
}
__device__ __forceinline__ void mma_bf16(float* d, const uint32_t* a,
                                         const uint32_t* b) {
    asm volatile("mma.sync.aligned.m16n8k16.row.col.f32.bf16.bf16.f32 "
        "{%0,%1,%2,%3}, {%4,%5,%6,%7}, {%8,%9}, {%0,%1,%2,%3};"
        : "+f"(d[0]), "+f"(d[1]), "+f"(d[2]), "+f"(d[3])
        : "r"(a[0]), "r"(a[1]), "r"(a[2]), "r"(a[3]), "r"(b[0]), "r"(b[1]));
}
__device__ __forceinline__ void cpa16(uint32_t s, const void* g) {
    asm volatile("cp.async.cg.shared.global [%0], [%1], 16;" :: "r"(s), "l"(g));
}
#define CP_COMMIT() asm volatile("cp.async.commit_group;" ::: "memory")
#define CP_WAIT(n)  asm volatile("cp.async.wait_group %0;" :: "n"(n) : "memory")

// ===========================================================================
// K0: int width detect + convert + p2p map (one block)
// ===========================================================================
__global__ void k_prep(const int* __restrict__ posw, const int* __restrict__ htsw) {
    __shared__ int s_pos64, s_hts64;
    if (threadIdx.x == 0) {
        int nz = 0;
        for (int w = 1; w < 33; w += 2) nz |= posw[w];
        s_pos64 = (nz == 0) ? 1 : 0;
        nz = 0;
        for (int w = 1; w < 33; w += 2) nz |= htsw[w];
        s_hts64 = (nz == 0) ? 1 : 0;
    }
    __syncthreads();
    int sp = s_pos64 ? 2 : 1;
    for (int t = threadIdx.x; t < B_*NE_*M_; t += blockDim.x)
        g_pos[t] = posw[(size_t)t * sp] + 1;          // fold +OFFSET
    int sh = s_hts64 ? 2 : 1;
    for (int t = threadIdx.x; t < B_*P_*2; t += blockDim.x)
        g_ht[t] = htsw[(size_t)t * sh];
    __syncthreads();
    for (int t = threadIdx.x; t < B_*P_; t += blockDim.x) {
        int b = t / P_;
        int i = g_ht[(size_t)t * 2 + 0];
        int j = g_ht[(size_t)t * 2 + 1];
        g_p2p[(b * NE_ + i) * NE_ + j] = t - b * P_;
    }
}

// ===========================================================================
// K1: entity_embed  (grid = B*NE, block = D)
// ===========================================================================
__global__ void k_entity_embed(const float* __restrict__ so,
                               const float* __restrict__ mask,
                               float* __restrict__ out_ee) {
    int be = blockIdx.x;
    int b = be / NE_;
    int d = threadIdx.x;

    __shared__ int   s_row[M_];
    __shared__ float s_mk[M_];
    if (threadIdx.x < M_) {
        s_mk[threadIdx.x]  = mask[(size_t)be * M_ + threadIdx.x];
        s_row[threadIdx.x] = g_pos[be * M_ + threadIdx.x];
    }
    __syncthreads();

    float v[M_];
    float mx = -INFINITY;
#pragma unroll
    for (int m = 0; m < M_; m++) {
        if (s_mk[m] > 0.f) {
            v[m] = so[((size_t)b * L_ + s_row[m]) * D_ + d];
            mx = fmaxf(mx, v[m]);
        } else v[m] = -INFINITY;
    }
    float s = 0.f;
#pragma unroll
    for (int m = 0; m < M_; m++) s += __expf(v[m] - mx);
    out_ee[(size_t)be * D_ + d] = logf(s) + mx;
}

// ===========================================================================
// K2: entity_att — float4, one shot.  grid = B*NE*H, block = 256
// ===========================================================================
__global__ __launch_bounds__(256)
void k_entity_att(const float* __restrict__ att,
                  const float* __restrict__ mask) {
    int id = blockIdx.x;
    int h  = id % H_;
    int be = id / H_;
    int b  = be / NE_;
    int e  = be % NE_;

    __shared__ int   s_row[M_];
    __shared__ float s_mk[M_];
    if (threadIdx.x < M_) {
        s_mk[threadIdx.x]  = mask[(size_t)be * M_ + threadIdx.x];
        s_row[threadIdx.x] = g_pos[be * M_ + threadIdx.x];
    }
    __syncthreads();

    float cnt = 0.f;
#pragma unroll
    for (int m = 0; m < M_; m++) cnt += s_mk[m];
    float inv = 1.f / cnt;

    const float4* a4 = (const float4*)(att + ((size_t)(b * H_ + h)) * L_ * L_);
    float4* e4 = (float4*)(g_ea + ((size_t)((b * H_ + h) * NE_ + e)) * L_);

    int t = threadIdx.x;                  // 256 threads x float4 = full row
    float4 acc = make_float4(0.f, 0.f, 0.f, 0.f);
#pragma unroll
    for (int m = 0; m < M_; m++) {
        if (s_mk[m] > 0.f) {
            float4 v = a4[(size_t)s_row[m] * 256 + t];
            acc.x += v.x; acc.y += v.y; acc.z += v.z; acc.w += v.w;
        }
    }
    acc.x *= inv; acc.y *= inv; acc.z *= inv; acc.w *= inv;
    e4[t] = acc;
}

// ===========================================================================
// K2b: transpose + bf16-split SO -> g_Bhi/g_Blo [b, d, l]
// ===========================================================================
__global__ void k_transpose(const float* __restrict__ so) {
    __shared__ float t[32][33];
    int b  = blockIdx.z;
    int l0 = blockIdx.x * 32;
    int d0 = blockIdx.y * 32;
    int tx = threadIdx.x, ty = threadIdx.y;

#pragma unroll
    for (int i = 0; i < 4; i++) {
        int l = l0 + ty + i * 8;
        t[ty + i * 8][tx] = so[((size_t)b * L_ + l) * D_ + d0 + tx];
    }
    __syncthreads();
#pragma unroll
    for (int i = 0; i < 4; i++) {
        int d = d0 + ty + i * 8;
        float v = t[tx][ty + i * 8];
        __nv_bfloat16 hi = __float2bfloat16(v);
        __nv_bfloat16 lo = __float2bfloat16(v - __bfloat162float(hi));
        size_t o = ((size_t)(b * D_ + d)) * L_ + l0 + tx;
        g_Bhi[o] = hi;
        g_Blo[o] = lo;
    }
}

// ===========================================================================
// K3: pair attention — float4 loads, one shot.  grid = B*NPU, block = 256
// ===========================================================================
__global__ __launch_bounds__(256)
void k_pair_att() {
    int bq = blockIdx.x;
    int b = bq / NPU, q = bq % NPU;

    int i = 0, rem = q;
    while (rem >= NE_ - 1 - i) { rem -= NE_ - 1 - i; i++; }
    int j = i + 1 + rem;

    const float4* ea4 = (const float4*)(g_ea + (size_t)b * H_ * NE_ * L_);
    int t = threadIdx.x;                  // 256 threads x 4 l = full row

    float4 x = make_float4(0.f, 0.f, 0.f, 0.f);
#pragma unroll
    for (int h = 0; h < H_; h++) {
        float4 a = ea4[(size_t)(h * NE_ + i) * 256 + t];
        float4 c = ea4[(size_t)(h * NE_ + j) * 256 + t];
        x.x = fmaf(a.x, c.x, x.x);
        x.y = fmaf(a.y, c.y, x.y);
        x.z = fmaf(a.z, c.z, x.z);
        x.w = fmaf(a.w, c.w, x.w);
    }

    size_t rowbase = ((size_t)(b * MP + q)) * L_;
    __nv_bfloat16 hv[4], lv[4];
    float xs[4] = {x.x, x.y, x.z, x.w};
#pragma unroll
    for (int c = 0; c < 4; c++) {
        hv[c] = __float2bfloat16(xs[c]);
        lv[c] = __float2bfloat16(xs[c] - __bfloat162float(hv[c]));
    }
    *(uint2*)&g_Xhi[rowbase + 4 * t] = *(uint2*)hv;
    *(uint2*)&g_Xlo[rowbase + 4 * t] = *(uint2*)lv;

    float lsum = x.x + x.y + x.z + x.w;
    __shared__ float red[256];
    red[t] = lsum;
    __syncthreads();
    for (int s = 128; s > 0; s >>= 1) {
        if (t < s) red[t] += red[t + s];
        __syncthreads();
    }
    if (t == 0)
        g_scale[bq] = 1.f / (red[0] + EPS_H);
}

// ===========================================================================
// K4: mma.sync bf16x3 GEMM, cp.async double-buffered.
//     CTA tile 128(M) x 64(N), BK=32, 256 thr (8 warps = 4m x 2n, 32x32 each).
//     grid = (D/64, MP/128, B).  2 CTAs/SM.
// SMEM stage (30720 B): A_hi[128][40]b16 @0, A_lo @10240,
//                       B_hi[64][40]b16 @20480, B_lo @25600.  2 stages.
// Epilogue reuses smem as C[128][68] f32.
// ===========================================================================
#define TS2    80                 // padded row stride in bytes (40 bf16)
#define STG    30720
#define SB_OFF 20480
#define CSTRIDE 68
#define SM_TOT (2*STG)            // 61440

__global__ __launch_bounds__(256, 2)
void k_gemm_mma(float* __restrict__ out) {
    extern __shared__ char smem[];
    uint32_t sb = smem_u32(smem);

    int tid = threadIdx.x;
    int wid = tid >> 5, lane = tid & 31;
    int gid = lane >> 2, tig = lane & 3;
    int wm = wid >> 1, wn = wid & 1;         // 4(m) x 2(n)
    int b  = blockIdx.z;
    int m0 = blockIdx.y * 128;
    int n0 = blockIdx.x * 64;

    const uint4* Ahi = (const uint4*)g_Xhi;  // row stride 128 uint4
    const uint4* Alo = (const uint4*)g_Xlo;
    const uint4* Bhi = (const uint4*)g_Bhi;
    const uint4* Blo = (const uint4*)g_Blo;
    int arow0 = (b * MP + m0) * 128;
    int brow0 = (b * D_ + n0) * 128;

    // load mapping
    int a_row = tid >> 2, a_seg = tid & 3;      // A: 512 chunks, 2/thread
    int b_row = tid >> 2, b_seg = tid & 3;      // B: 256 chunks, 1/thread

    // ldmatrix lane addressing
    int sub = lane >> 3, lrow = lane & 7;
    int a_r = wm * 32 + lrow + (sub & 1) * 8;
    int a_k = (sub >> 1) * 8;
    int b_r = wn * 32 + lrow + (sub >> 1) * 8;
    int b_k = (sub & 1) * 8;

    float acc[2][4][4];
#pragma unroll
    for (int mt = 0; mt < 2; mt++)
#pragma unroll
        for (int nt = 0; nt < 4; nt++)
#pragma unroll
            for (int r = 0; r < 4; r++) acc[mt][nt][r] = 0.f;

#define LOAD_STAGE(it, stg) do {                                            \
    uint32_t s0 = sb + (stg) * STG;                                         \
    _Pragma("unroll")                                                       \
    for (int c = 0; c < 2; c++) {                                           \
        int idx = tid + c * 256;                                            \
        int row = idx >> 2, seg = idx & 3;                                  \
        int gi = arow0 + row * 128 + (it) * 4 + seg;                        \
        uint32_t sa = s0 + row * TS2 + seg * 16;                            \
        cpa16(sa,         Ahi + gi);                                        \
        cpa16(sa + 10240, Alo + gi);                                        \
    }                                                                       \
    {                                                                       \
        int gi = brow0 + b_row * 128 + (it) * 4 + b_seg;                    \
        uint32_t sB = s0 + SB_OFF + b_row * TS2 + b_seg * 16;               \
        cpa16(sB,        Bhi + gi);                                         \
        cpa16(sB + 5120, Blo + gi);                                         \
    }                                                                       \
} while (0)

    LOAD_STAGE(0, 0); CP_COMMIT();
    LOAD_STAGE(1, 1); CP_COMMIT();

    for (int it = 0; it < 32; it++) {
        if (it + 1 < 32) { CP_WAIT(1); } else { CP_WAIT(0); }
        __syncthreads();

        uint32_t s0 = sb + (it & 1) * STG;
#pragma unroll
        for (int ks = 0; ks < 2; ks++) {
            uint32_t ah[2][4], al[2][4], bh[4][2], bl[4][2];
            int kofs = (ks * 16 + a_k) * 2;
#pragma unroll
            for (int mt = 0; mt < 2; mt++) {
                uint32_t ad = s0 + (a_r + mt * 16) * TS2 + kofs;
                ldm_x4(ah[mt], ad);
                ldm_x4(al[mt], ad + 10240);
            }
            int kofsb = (ks * 16 + b_k) * 2;
#pragma unroll
            for (int np = 0; np < 2; np++) {
                uint32_t bd = s0 + SB_OFF + (b_r + np * 16) * TS2 + kofsb;
                uint32_t t4[4];
                ldm_x4(t4, bd);
                bh[np*2][0] = t4[0]; bh[np*2][1] = t4[1];
                bh[np*2+1][0] = t4[2]; bh[np*2+1][1] = t4[3];
                ldm_x4(t4, bd + 5120);
                bl[np*2][0] = t4[0]; bl[np*2][1] = t4[1];
                bl[np*2+1][0] = t4[2]; bl[np*2+1][1] = t4[3];
            }
#pragma unroll
            for (int mt = 0; mt < 2; mt++)
#pragma unroll
                for (int nt = 0; nt < 4; nt++) {
                    mma_bf16(acc[mt][nt], ah[mt], bh[nt]);
                    mma_bf16(acc[mt][nt], ah[mt], bl[nt]);
                    mma_bf16(acc[mt][nt], al[mt], bh[nt]);
                }
        }
        __syncthreads();
        if (it + 2 < 32) { LOAD_STAGE(it + 2, it & 1); CP_COMMIT(); }
    }

    // -------- epilogue: acc -> SMEM C, scaled dual scatter --------
    __shared__ float s_sc[128];
    __shared__ int   s_p1[128], s_p2[128];

    float* C = (float*)smem;
#pragma unroll
    for (int mt = 0; mt < 2; mt++) {
        int rm = wm * 32 + mt * 16 + gid;
#pragma unroll
        for (int nt = 0; nt < 4; nt++) {
            int cn = wn * 32 + nt * 8 + tig * 2;
            *(float2*)&C[rm * CSTRIDE + cn]       = make_float2(acc[mt][nt][0], acc[mt][nt][1]);
            *(float2*)&C[(rm + 8) * CSTRIDE + cn] = make_float2(acc[mt][nt][2], acc[mt][nt][3]);
        }
    }
    if (tid < 128) {
        int q = m0 + tid;
        if (q < NPU) {
            s_sc[tid] = g_scale[b * NPU + q];
            int i = 0, rem = q;
            while (rem >= NE_ - 1 - i) { rem -= NE_ - 1 - i; i++; }
            int j = i + 1 + rem;
            s_p1[tid] = g_p2p[(b * NE_ + i) * NE_ + j];
            s_p2[tid] = g_p2p[(b * NE_ + j) * NE_ + i];
        }
    }
    __syncthreads();

    int r    = tid >> 1;
    int half = (tid & 1) * 32;
    int q = m0 + r;
    if (q < NPU) {
        float sc = s_sc[r];
        float* ht = out + (size_t)B_ * NE_ * D_;
        size_t o1 = ((size_t)(b * P_ + s_p1[r])) * D_ + n0 + half;
        size_t o2 = ((size_t)(b * P_ + s_p2[r])) * D_ + n0 + half;
        const float* crow = &C[r * CSTRIDE + half];
#pragma unroll
        for (int c = 0; c < 32; c += 4) {
            float4 v = make_float4(crow[c] * sc, crow[c + 1] * sc,
                                   crow[c + 2] * sc, crow[c + 3] * sc);
            *(float4*)&ht[o1 + c] = v;
            *(float4*)&ht[o2 + c] = v;
        }
    }
}

// ===========================================================================
extern "C" void kernel_launch(void* const* d_in, const int* in_sizes, int n_in,
                              void* d_out, int out_size) {
    const float* so   = nullptr;
    const float* att  = nullptr;
    const float* mask = nullptr;
    const int*   posw = nullptr;
    const int*   htsw = nullptr;

    for (int k = 0; k < n_in; k++) {
        int sz = in_sizes[k];
        if      (sz == SZ_SO)  so   = (const float*)d_in[k];
        else if (sz == SZ_ATT) att  = (const float*)d_in[k];
        else if (sz == SZ_HTS) htsw = (const int*)d_in[k];
        else if (sz == SZ_MSK) {
            if (!mask) mask = (const float*)d_in[k];
            else       posw = (const int*)d_in[k];
        }
    }
    float* out = (float*)d_out;

    cudaFuncSetAttribute(k_gemm_mma,
                         cudaFuncAttributeMaxDynamicSharedMemorySize, SM_TOT);

    k_prep<<<1, 1024>>>(posw, htsw);
    k_entity_embed<<<B_ * NE_, D_>>>(so, mask, out);
    {
        dim3 g(L_ / 32, D_ / 32, B_);
        dim3 t(32, 8);
        k_transpose<<<g, t>>>(so);
    }
    k_entity_att<<<B_ * NE_ * H_, 256>>>(att, mask);
    k_pair_att<<<B_ * NPU, 256>>>();

    dim3 grid(D_ / 64, MP / 128, B_);
    k_gemm_mma<<<grid, 256, SM_TOT>>>(out);
}